// round 3
// baseline (speedup 1.0000x reference)
#include <cuda_runtime.h>
#include <math.h>

#define BSZ   512
#define NFEAT 512
#define HID   1000
#define TTOT  65
#define TSEQ  64
#define NGAP  16

// ---------------- scratch layout (one big __device__ array, with aliasing) ---
// Live ranges:
//   Xp : phases 1-3 (input proj + scan). Dead after scan.
//   Hs : phases 2-6 (scan output, autoenc input, decode seed). Live long.
//   Z1 : phase 4 gemm1 out / gemm2 in. Dead once Z2 written.
//   Z2 : phase 4 gemm2 out / gemm3 in. Dead once Y written.
//   Y  : phase 4 gemm3 out, used by loss1 + decode g=0.  -> alias into Z1.
//   decode scratch (CP, HD, Z1d, Z2d, Xg) : phase 6-7.   -> alias into Xp.
#define SZ_XP   (512L*65*512)                 // 17039360
#define SZ_HS   (512L*64*512)                 // 16777216
#define SZ_Z1   (512L*64*1000)                // 32768000
#define SZ_Z2   SZ_Z1
#define SZ_Y    SZ_HS

#define OFF_XP  0L
#define OFF_HS  (OFF_XP+SZ_XP)
#define OFF_Z1  (OFF_HS+SZ_HS)
#define OFF_Z2  (OFF_Z1+SZ_Z1)
#define OFF_Y   OFF_Z1                        // alias: Y overlays Z1 (dead)
#define TOTAL_BUF (OFF_Z2+SZ_Z2)

// decode-phase scratch overlays Xp (dead after scan)
#define DOFF_CP   OFF_XP                      // 512*512
#define DOFF_HD   (DOFF_CP + 512L*512)        // 2*512*512
#define DOFF_Z1D  (DOFF_HD + 2L*512*512)      // 512*1000
#define DOFF_Z2D  (DOFF_Z1D + 512L*1000)      // 512*1000
#define DOFF_XG   (DOFF_Z2D + 512L*1000)      // 16*512*512 = 4194304
#define DOFF_BS   (DOFF_XG + 16L*512*512)     // 512
// DOFF_BS + 512 = 262144+524288+512000+512000+4194304+512 = 6005248 < SZ_XP OK
// NOTE: bsum lives in Xp region but is written BEFORE Xp and only read by
// phase-1 (input proj) and decode. Phase-1 writes Xp rows; bsum sits at
// offset 6004736..6005247 inside Xp -> would be clobbered by phase 1!
// So bsum gets its own tiny slot instead:
#define OFF_BS  TOTAL_BUF
#define TOTAL_BUF2 (TOTAL_BUF + 512L)

__device__ float  g_buf[TOTAL_BUF2];
__device__ double g_loss[2];

// ---------------- reductions ----------------
__inline__ __device__ float blockReduceSum(float v) {
    __shared__ float s[32];
    int lane = threadIdx.x & 31;
    int wid  = threadIdx.x >> 5;
    #pragma unroll
    for (int o = 16; o > 0; o >>= 1) v += __shfl_down_sync(0xffffffffu, v, o);
    if (lane == 0) s[wid] = v;
    __syncthreads();
    int nwarp = blockDim.x >> 5;
    v = (threadIdx.x < nwarp) ? s[lane] : 0.f;
    if (wid == 0) {
        #pragma unroll
        for (int o = 16; o > 0; o >>= 1) v += __shfl_down_sync(0xffffffffu, v, o);
    }
    return v;
}

// ---------------- generic fused GEMM: C = epi(A @ W^T) ----------------
// A: M x K (row stride lda), W: N x K (row stride K), C: M x N (row stride ldc)
// mode 0: C = acc + bias[n]
// mode 1: C = tanh(acc + pre[m*ldpre + n])           (pre already holds biases)
// mode 2: C = (acc + bias[n] - rm[n]) * (g[n]*rsqrt(rv[n]+eps)) + beta[n]
template<int BM, int BN, int BK, int TM, int TN, int NT>
__global__ void __launch_bounds__(NT)
gemm_kernel(
    const float* __restrict__ A, int lda,
    const float* __restrict__ W,
    float* __restrict__ C, int ldc,
    int M, int N, int K,
    int mode,
    const float* __restrict__ bias,
    const float* __restrict__ pre, int ldpre,
    const float* __restrict__ gsc, const float* __restrict__ beta,
    const float* __restrict__ rm,  const float* __restrict__ rv)
{
    __shared__ __align__(16) float As[BK][BM + 4];
    __shared__ __align__(16) float Ws[BK][BN + 4];

    const int tid = threadIdx.x;
    const int bm = blockIdx.y * BM;
    const int bn = blockIdx.x * BN;

    constexpr int TX = BN / TN;          // threads along n
    const int tx = tid % TX;
    const int ty = tid / TX;

    float acc[TM][TN];
    #pragma unroll
    for (int i = 0; i < TM; i++)
        #pragma unroll
        for (int j = 0; j < TN; j++) acc[i][j] = 0.f;

    constexpr int LA = (BM * BK) / (NT * 4);
    constexpr int LB = (BN * BK) / (NT * 4);

    for (int k0 = 0; k0 < K; k0 += BK) {
        #pragma unroll
        for (int l = 0; l < LA; l++) {
            int idx = (tid + l * NT) * 4;
            int r = idx / BK, c = idx % BK;
            float4 v = make_float4(0.f, 0.f, 0.f, 0.f);
            int m = bm + r;
            if (m < M && (k0 + c) < K)
                v = *reinterpret_cast<const float4*>(A + (long)m * lda + k0 + c);
            As[c + 0][r] = v.x; As[c + 1][r] = v.y;
            As[c + 2][r] = v.z; As[c + 3][r] = v.w;
        }
        #pragma unroll
        for (int l = 0; l < LB; l++) {
            int idx = (tid + l * NT) * 4;
            int r = idx / BK, c = idx % BK;
            float4 v = make_float4(0.f, 0.f, 0.f, 0.f);
            int n = bn + r;
            if (n < N && (k0 + c) < K)
                v = *reinterpret_cast<const float4*>(W + (long)n * K + k0 + c);
            Ws[c + 0][r] = v.x; Ws[c + 1][r] = v.y;
            Ws[c + 2][r] = v.z; Ws[c + 3][r] = v.w;
        }
        __syncthreads();

        #pragma unroll
        for (int kk = 0; kk < BK; kk++) {
            float ra[TM], rb[TN];
            #pragma unroll
            for (int i = 0; i < TM; i += 4) {
                float4 v = *reinterpret_cast<const float4*>(&As[kk][ty * TM + i]);
                ra[i] = v.x; ra[i + 1] = v.y; ra[i + 2] = v.z; ra[i + 3] = v.w;
            }
            #pragma unroll
            for (int j = 0; j < TN; j += 4) {
                float4 v = *reinterpret_cast<const float4*>(&Ws[kk][tx * TN + j]);
                rb[j] = v.x; rb[j + 1] = v.y; rb[j + 2] = v.z; rb[j + 3] = v.w;
            }
            #pragma unroll
            for (int i = 0; i < TM; i++)
                #pragma unroll
                for (int j = 0; j < TN; j++)
                    acc[i][j] = fmaf(ra[i], rb[j], acc[i][j]);
        }
        __syncthreads();
    }

    // epilogue
    #pragma unroll
    for (int i = 0; i < TM; i++) {
        int m = bm + ty * TM + i;
        if (m >= M) continue;
        #pragma unroll
        for (int j = 0; j < TN; j += 4) {
            int n0 = bn + tx * TN + j;
            float vv[4];
            #pragma unroll
            for (int q = 0; q < 4; q++) {
                int n = n0 + q;
                float a = acc[i][j + q];
                float r = 0.f;
                if (n < N) {
                    if (mode == 0)      r = a + bias[n];
                    else if (mode == 1) r = tanhf(a + pre[(long)m * ldpre + n]);
                    else                r = (a + bias[n] - rm[n]) *
                                            (gsc[n] * rsqrtf(rv[n] + 1e-5f)) + beta[n];
                }
                vv[q] = r;
            }
            if (n0 + 3 < N) {
                float4 s = make_float4(vv[0], vv[1], vv[2], vv[3]);
                *reinterpret_cast<float4*>(C + (long)m * ldc + n0) = s;
            } else {
                for (int q = 0; q < 4; q++)
                    if (n0 + q < N) C[(long)m * ldc + n0 + q] = vv[q];
            }
        }
    }
}

// ---------------- elementwise kernels ----------------
__global__ void init_kernel(const float* __restrict__ b_ih,
                            const float* __restrict__ b_hh,
                            float* __restrict__ bsum) {
    int i = threadIdx.x;
    if (i < NFEAT) bsum[i] = b_ih[i] + b_hh[i];
    if (i < 2) g_loss[i] = 0.0;
}

// h_1 = tanh(Xp[:,0,:])  (h0 == 0)
__global__ void h1_kernel(const float* __restrict__ Xp, float* __restrict__ Hs) {
    int e = blockIdx.x * blockDim.x + threadIdx.x;
    if (e < BSZ * NFEAT) {
        int b = e >> 9, f = e & 511;
        Hs[((long)b * TSEQ) * NFEAT + f] = tanhf(Xp[((long)b * TTOT) * NFEAT + f]);
    }
}

// loss1: sum over (Y[b,t] - x[b,t+1])^2 for t in [0,62]
__global__ void loss1_kernel(const float* __restrict__ Y, const float* __restrict__ x) {
    const long total = (long)BSZ * 63 * NFEAT;
    float local = 0.f;
    for (long e = (long)blockIdx.x * blockDim.x + threadIdx.x; e < total;
         e += (long)gridDim.x * blockDim.x) {
        int f  = (int)(e & 511);
        long bt = e >> 9;
        int tt = (int)(bt % 63);
        int b  = (int)(bt / 63);
        float yv = Y[((long)b * TSEQ + tt) * NFEAT + f];
        float xv = x[((long)b * TTOT + tt + 1) * NFEAT + f];
        float d = yv - xv;
        local += d * d;
    }
    float s = blockReduceSum(local);
    if (threadIdx.x == 0) atomicAdd(&g_loss[0], (double)s);
}

// copy the decode-seed rows out of Y/Hs before their regions get reused
__global__ void seed_kernel(const float* __restrict__ Y,
                            const float* __restrict__ Hs,
                            float* __restrict__ xseed,   // BSZ x NFEAT
                            float* __restrict__ hseed) { // BSZ x NFEAT
    int e = blockIdx.x * blockDim.x + threadIdx.x;
    if (e < BSZ * NFEAT) {
        int b = e >> 9, f = e & 511;
        xseed[e] = Y[((long)b * TSEQ + (TSEQ - 1)) * NFEAT + f];
        hseed[e] = Hs[((long)b * TSEQ + (TSEQ - 1)) * NFEAT + f];
    }
}

// gather x_pred = Xg[t[b]-1][b,:], write to out, accumulate loss2
__global__ void final_kernel(const float* __restrict__ Xg, const float* __restrict__ x,
                             const int* __restrict__ t, float* __restrict__ out,
                             int out_size) {
    int e = blockIdx.x * blockDim.x + threadIdx.x;
    float local = 0.f;
    if (e < BSZ * NFEAT) {
        int b = e >> 9, f = e & 511;
        int gp = t[b] - 1;
        float v = Xg[(long)gp * BSZ * NFEAT + e];
        if (e < out_size) out[e] = v;
        float xf = x[((long)b * TTOT + TSEQ) * NFEAT + f];
        float d = v - xf;
        local = d * d;
    }
    float s = blockReduceSum(local);
    if (threadIdx.x == 0) atomicAdd(&g_loss[1], (double)s);
}

__global__ void write_loss_kernel(float* __restrict__ out, int out_size) {
    const double n1 = 16515072.0;  // 63*512*512
    const double n2 = 262144.0;    // 512*512
    double l = g_loss[0] / (n1 * n1) + g_loss[1] / (n2 * n2);
    for (int i = BSZ * NFEAT + threadIdx.x; i < out_size; i += blockDim.x)
        out[i] = (float)l;
}

// ---------------- host launchers ----------------
static inline void gemm_big(const float* A, int lda, const float* W,
                            float* C, int ldc, int M, int N, int K, int mode,
                            const float* bias, const float* pre, int ldpre,
                            const float* g, const float* beta,
                            const float* rm, const float* rv) {
    dim3 grid((N + 127) / 128, (M + 127) / 128);
    gemm_kernel<128, 128, 8, 8, 8, 256><<<grid, 256>>>(
        A, lda, W, C, ldc, M, N, K, mode, bias, pre, ldpre, g, beta, rm, rv);
}

static inline void gemm_small(const float* A, int lda, const float* W,
                              float* C, int ldc, int M, int N, int K, int mode,
                              const float* bias, const float* pre, int ldpre,
                              const float* g, const float* beta,
                              const float* rm, const float* rv) {
    dim3 grid((N + 63) / 64, (M + 63) / 64);
    gemm_kernel<64, 64, 16, 4, 4, 256><<<grid, 256>>>(
        A, lda, W, C, ldc, M, N, K, mode, bias, pre, ldpre, g, beta, rm, rv);
}

extern "C" void kernel_launch(void* const* d_in, const int* in_sizes, int n_in,
                              void* d_out, int out_size) {
    const float* x     = (const float*)d_in[0];
    const int*   t     = (const int*)  d_in[1];
    const float* W_ih  = (const float*)d_in[2];
    const float* W_hh  = (const float*)d_in[3];
    const float* b_ih  = (const float*)d_in[4];
    const float* b_hh  = (const float*)d_in[5];
    const float* W1    = (const float*)d_in[6];
    const float* b1    = (const float*)d_in[7];
    const float* g1    = (const float*)d_in[8];
    const float* beta1 = (const float*)d_in[9];
    const float* rm1   = (const float*)d_in[10];
    const float* rv1   = (const float*)d_in[11];
    const float* W2    = (const float*)d_in[12];
    const float* b2    = (const float*)d_in[13];
    const float* g2    = (const float*)d_in[14];
    const float* beta2 = (const float*)d_in[15];
    const float* rm2   = (const float*)d_in[16];
    const float* rv2   = (const float*)d_in[17];
    const float* W3    = (const float*)d_in[18];
    const float* b3    = (const float*)d_in[19];
    const float* g3    = (const float*)d_in[20];
    const float* beta3 = (const float*)d_in[21];
    const float* rm3   = (const float*)d_in[22];
    const float* rv3   = (const float*)d_in[23];
    float* out = (float*)d_out;

    float* buf = nullptr;
    cudaGetSymbolAddress((void**)&buf, g_buf);

    float* Xp   = buf + OFF_XP;
    float* Hs   = buf + OFF_HS;
    float* Z1   = buf + OFF_Z1;
    float* Z2   = buf + OFF_Z2;
    float* Y    = buf + OFF_Y;    // aliases Z1 (Z1 dead before Y written)
    float* bsum = buf + OFF_BS;

    // decode scratch overlays Xp (dead after phase 3); seeds copied out first
    float* CP    = buf + DOFF_CP;
    float* HD    = buf + DOFF_HD;     // [0]: xseed+h ping-pong (h), 2 slots
    float* Z1d   = buf + DOFF_Z1D;
    float* Z2d   = buf + DOFF_Z2D;
    float* Xg    = buf + DOFF_XG;
    float* hseed = HD;                       // slot 0 of HD used as h seed
    float* xseed = Xg + 15L * BSZ * NFEAT;   // park x seed in last Xg slot
                                             // (overwritten only at g=15,
                                             //  after it was consumed at g=0)

    // 0. init: bsum = b_ih + b_hh; zero loss accumulators
    init_kernel<<<1, 512>>>(b_ih, b_hh, bsum);

    // 1. Xp = x @ W_ih^T + bsum  (all 65 timesteps; t=64 unused, harmless)
    gemm_big(x, NFEAT, W_ih, Xp, NFEAT, BSZ * TTOT, NFEAT, NFEAT,
             0, bsum, nullptr, 0, nullptr, nullptr, nullptr, nullptr);

    // 2. h_1 = tanh(Xp[:,0,:])
    h1_kernel<<<(BSZ * NFEAT + 255) / 256, 256>>>(Xp, Hs);

    // 3. RNN scan: h_{t} = tanh(Xp[:,t,:] + h_{t-1} @ W_hh^T)
    for (int tt = 1; tt < TSEQ; tt++) {
        gemm_small(Hs + (long)(tt - 1) * NFEAT, TSEQ * NFEAT, W_hh,
                   Hs + (long)tt * NFEAT, TSEQ * NFEAT,
                   BSZ, NFEAT, NFEAT,
                   1, nullptr, Xp + (long)tt * NFEAT, TTOT * NFEAT,
                   nullptr, nullptr, nullptr, nullptr);
    }

    // 4. autoencoder on all B*T rows  (Z1 -> Z2 -> Y where Y aliases Z1;
    //    legal: gemm3 reads only Z2, writes Y region = old Z1)
    gemm_big(Hs, NFEAT, W1, Z1, HID, BSZ * TSEQ, HID, NFEAT,
             2, b1, nullptr, 0, g1, beta1, rm1, rv1);
    gemm_big(Z1, HID, W2, Z2, HID, BSZ * TSEQ, HID, HID,
             2, b2, nullptr, 0, g2, beta2, rm2, rv2);
    gemm_big(Z2, HID, W3, Y, NFEAT, BSZ * TSEQ, NFEAT, HID,
             2, b3, nullptr, 0, g3, beta3, rm3, rv3);

    // 5. loss1 accumulation
    loss1_kernel<<<2048, 256>>>(Y, x);

    // 5b. copy decode seeds (Y/Hs last timestep) into decode scratch
    seed_kernel<<<(BSZ * NFEAT + 255) / 256, 256>>>(Y, Hs, xseed, hseed);

    // 6. decode loop (16 sequential steps)
    for (int g = 0; g < NGAP; g++) {
        const float* xhat = (g == 0) ? xseed : (Xg + (long)(g - 1) * BSZ * NFEAT);
        const float* hhat = (g == 0) ? hseed : (HD + (long)((g - 1) & 1) * BSZ * NFEAT);
        float*       hnew = HD + (long)(g & 1) * BSZ * NFEAT;
        // note: g=0 reads hseed (HD slot 0) and writes hnew (HD slot 0).
        // gemm reads all of A before writing C? NOT guaranteed across CTAs.
        // Avoid by writing g=0's h into slot 1 instead:
        if (g == 0) hnew = HD + (long)BSZ * NFEAT;
        if (g >= 1) {
            hhat = HD + (long)(((g - 1) + 1) & 1 ? 1 : 0) * BSZ * NFEAT;
            // keep simple alternation consistent with the override above:
            // h for step g lives in slot ((g+1)&1)
            hhat = HD + (long)((g & 1) ? 1 : 0) * BSZ * NFEAT;
            hnew = HD + (long)((g & 1) ? 0 : 1) * BSZ * NFEAT;
        }

        // cellPre = x_hat @ W_ih^T + bsum
        gemm_small(xhat, NFEAT, W_ih, CP, NFEAT, BSZ, NFEAT, NFEAT,
                   0, bsum, nullptr, 0, nullptr, nullptr, nullptr, nullptr);
        // h2 = tanh(cellPre + h_hat @ W_hh^T)
        gemm_small(hhat, NFEAT, W_hh, hnew, NFEAT, BSZ, NFEAT, NFEAT,
                   1, nullptr, CP, NFEAT, nullptr, nullptr, nullptr, nullptr);
        // autoencoder
        gemm_small(hnew, NFEAT, W1, Z1d, HID, BSZ, HID, NFEAT,
                   2, b1, nullptr, 0, g1, beta1, rm1, rv1);
        gemm_small(Z1d, HID, W2, Z2d, HID, BSZ, HID, HID,
                   2, b2, nullptr, 0, g2, beta2, rm2, rv2);
        gemm_small(Z2d, HID, W3, Xg + (long)g * BSZ * NFEAT, NFEAT, BSZ, NFEAT, HID,
                   2, b3, nullptr, 0, g3, beta3, rm3, rv3);
    }

    // 7. gather x_pred, loss2
    final_kernel<<<(BSZ * NFEAT + 255) / 256, 256>>>(Xg, x, t, out, out_size);

    // 8. final loss
    write_loss_kernel<<<1, 256>>>(out, out_size);
}

// round 4
// speedup vs baseline: 1.1363x; 1.1363x over previous
#include <cuda_runtime.h>
#include <math.h>

#define BSZ   512
#define NFEAT 512
#define HID   1000
#define TTOT  65
#define TSEQ  64
#define NGAP  16

// ---------------- scratch layout (one big __device__ array, aliased) --------
#define SZ_XP   (512L*65*512)
#define SZ_HS   (512L*64*512)
#define SZ_Z1   (512L*64*1000)
#define SZ_Z2   SZ_Z1

#define OFF_XP  0L
#define OFF_HS  (OFF_XP+SZ_XP)
#define OFF_Z1  (OFF_HS+SZ_HS)
#define OFF_Z2  (OFF_Z1+SZ_Z1)
#define OFF_Y   OFF_Z1                        // Y overlays Z1 (Z1 dead by then)
#define OFF_WT  (OFF_Z2+SZ_Z2)                // W_hh^T  (512*512)
#define OFF_WC  (OFF_WT+512L*512)             // W_cat   (512*1024)
#define OFF_BS  (OFF_WC+512L*1024)            // bsum    (512)
#define TOTAL_BUF (OFF_BS+512L)

// decode-phase scratch overlays Xp (dead after scan)
#define DOFF_S0   0L                          // state [512 x 1024] = [x|h]
#define DOFF_S1   (DOFF_S0 + 512L*1024)
#define DOFF_Z1D  (DOFF_S1 + 512L*1024)
#define DOFF_Z2D  (DOFF_Z1D + 512L*1000)
#define DOFF_XG   (DOFF_Z2D + 512L*1000)      // 16 x 512 x 512

__device__ float  g_buf[TOTAL_BUF];
__device__ double g_loss[2];

// ---------------- reductions ----------------
__inline__ __device__ float blockReduceSum(float v) {
    __shared__ float s[32];
    int lane = threadIdx.x & 31;
    int wid  = threadIdx.x >> 5;
    #pragma unroll
    for (int o = 16; o > 0; o >>= 1) v += __shfl_down_sync(0xffffffffu, v, o);
    if (lane == 0) s[wid] = v;
    __syncthreads();
    int nwarp = blockDim.x >> 5;
    v = (threadIdx.x < nwarp) ? s[lane] : 0.f;
    if (wid == 0) {
        #pragma unroll
        for (int o = 16; o > 0; o >>= 1) v += __shfl_down_sync(0xffffffffu, v, o);
    }
    return v;
}

// ---------------- generic fused GEMM: C = epi(A @ W^T) ----------------
// A: M x K (row stride lda), W: N x K (row stride K), C: M x N (row stride ldc)
// mode 0: C = acc + bias[n]
// mode 2: C = (acc + bias[n] - rm[n]) * (g[n]*rsqrt(rv[n]+eps)) + beta[n]
// mode 3: C = tanh(acc + bias[n])
// C2 (optional): second destination with its own ldc2
template<int BM, int BN, int BK, int TM, int TN, int NT>
__global__ void __launch_bounds__(NT)
gemm_kernel(
    const float* __restrict__ A, int lda,
    const float* __restrict__ W,
    float* __restrict__ C, int ldc,
    float* __restrict__ C2, int ldc2,
    int M, int N, int K,
    int mode,
    const float* __restrict__ bias,
    const float* __restrict__ gsc, const float* __restrict__ beta,
    const float* __restrict__ rm,  const float* __restrict__ rv)
{
    __shared__ __align__(16) float As[BK][BM + 4];
    __shared__ __align__(16) float Ws[BK][BN + 4];

    const int tid = threadIdx.x;
    const int bm = blockIdx.y * BM;
    const int bn = blockIdx.x * BN;

    constexpr int TX = BN / TN;          // threads along n
    const int tx = tid % TX;
    const int ty = tid / TX;

    float acc[TM][TN];
    #pragma unroll
    for (int i = 0; i < TM; i++)
        #pragma unroll
        for (int j = 0; j < TN; j++) acc[i][j] = 0.f;

    constexpr int LA = (BM * BK) / (NT * 4);
    constexpr int LB = (BN * BK) / (NT * 4);

    for (int k0 = 0; k0 < K; k0 += BK) {
        #pragma unroll
        for (int l = 0; l < LA; l++) {
            int idx = (tid + l * NT) * 4;
            int r = idx / BK, c = idx % BK;
            float4 v = make_float4(0.f, 0.f, 0.f, 0.f);
            int m = bm + r;
            if (m < M && (k0 + c) < K)
                v = *reinterpret_cast<const float4*>(A + (long)m * lda + k0 + c);
            As[c + 0][r] = v.x; As[c + 1][r] = v.y;
            As[c + 2][r] = v.z; As[c + 3][r] = v.w;
        }
        #pragma unroll
        for (int l = 0; l < LB; l++) {
            int idx = (tid + l * NT) * 4;
            int r = idx / BK, c = idx % BK;
            float4 v = make_float4(0.f, 0.f, 0.f, 0.f);
            int n = bn + r;
            if (n < N && (k0 + c) < K)
                v = *reinterpret_cast<const float4*>(W + (long)n * K + k0 + c);
            Ws[c + 0][r] = v.x; Ws[c + 1][r] = v.y;
            Ws[c + 2][r] = v.z; Ws[c + 3][r] = v.w;
        }
        __syncthreads();

        #pragma unroll
        for (int kk = 0; kk < BK; kk++) {
            float ra[TM], rb[TN];
            #pragma unroll
            for (int i = 0; i < TM; i += 4) {
                float4 v = *reinterpret_cast<const float4*>(&As[kk][ty * TM + i]);
                ra[i] = v.x; ra[i + 1] = v.y; ra[i + 2] = v.z; ra[i + 3] = v.w;
            }
            #pragma unroll
            for (int j = 0; j < TN; j += 4) {
                float4 v = *reinterpret_cast<const float4*>(&Ws[kk][tx * TN + j]);
                rb[j] = v.x; rb[j + 1] = v.y; rb[j + 2] = v.z; rb[j + 3] = v.w;
            }
            #pragma unroll
            for (int i = 0; i < TM; i++)
                #pragma unroll
                for (int j = 0; j < TN; j++)
                    acc[i][j] = fmaf(ra[i], rb[j], acc[i][j]);
        }
        __syncthreads();
    }

    // epilogue
    #pragma unroll
    for (int i = 0; i < TM; i++) {
        int m = bm + ty * TM + i;
        if (m >= M) continue;
        #pragma unroll
        for (int j = 0; j < TN; j += 4) {
            int n0 = bn + tx * TN + j;
            float vv[4];
            #pragma unroll
            for (int q = 0; q < 4; q++) {
                int n = n0 + q;
                float a = acc[i][j + q];
                float r = 0.f;
                if (n < N) {
                    if (mode == 0)      r = a + bias[n];
                    else if (mode == 3) r = tanhf(a + bias[n]);
                    else                r = (a + bias[n] - rm[n]) *
                                            (gsc[n] * rsqrtf(rv[n] + 1e-5f)) + beta[n];
                }
                vv[q] = r;
            }
            if (n0 + 3 < N) {
                float4 s = make_float4(vv[0], vv[1], vv[2], vv[3]);
                *reinterpret_cast<float4*>(C + (long)m * ldc + n0) = s;
                if (C2)
                    *reinterpret_cast<float4*>(C2 + (long)m * ldc2 + n0) = s;
            } else {
                for (int q = 0; q < 4; q++)
                    if (n0 + q < N) {
                        C[(long)m * ldc + n0 + q] = vv[q];
                        if (C2) C2[(long)m * ldc2 + n0 + q] = vv[q];
                    }
            }
        }
    }
}

// ---------------- persistent RNN scan ----------------
// Batch-parallel: CTA c owns batch rows 4c..4c+3, h kept in smem.
// h_t = tanh(Xp[:,t,:] + h_{t-1} @ W_hh^T), using WT (k-major) for coalescing.
__global__ void __launch_bounds__(256)
scan_kernel(const float* __restrict__ Xp, const float* __restrict__ WT,
            float* __restrict__ Hs)
{
    __shared__ __align__(16) float hs[4][NFEAT];
    const int tid = threadIdx.x;
    const int b0 = blockIdx.x * 4;
    const int n0 = tid * 2;          // this thread's two output columns

    // t = 0: h1 = tanh(Xp[:,0,:])  (h0 == 0)
    for (int i = tid; i < 4 * NFEAT; i += 256) {
        int r = i >> 9, f = i & 511;
        float v = tanhf(Xp[((long)(b0 + r) * TTOT) * NFEAT + f]);
        hs[r][f] = v;
        Hs[((long)(b0 + r) * TSEQ) * NFEAT + f] = v;
    }
    __syncthreads();

    for (int t = 1; t < TSEQ; t++) {
        float acc[4][2];
        #pragma unroll
        for (int r = 0; r < 4; r++) { acc[r][0] = 0.f; acc[r][1] = 0.f; }

        #pragma unroll 4
        for (int k = 0; k < NFEAT; k += 4) {
            float4 h0 = *reinterpret_cast<const float4*>(&hs[0][k]);
            float4 h1 = *reinterpret_cast<const float4*>(&hs[1][k]);
            float4 h2 = *reinterpret_cast<const float4*>(&hs[2][k]);
            float4 h3 = *reinterpret_cast<const float4*>(&hs[3][k]);
            #pragma unroll
            for (int kk = 0; kk < 4; kk++) {
                float2 w = *reinterpret_cast<const float2*>(
                    &WT[(long)(k + kk) * NFEAT + n0]);
                float v0 = (kk == 0) ? h0.x : (kk == 1) ? h0.y : (kk == 2) ? h0.z : h0.w;
                float v1 = (kk == 0) ? h1.x : (kk == 1) ? h1.y : (kk == 2) ? h1.z : h1.w;
                float v2 = (kk == 0) ? h2.x : (kk == 1) ? h2.y : (kk == 2) ? h2.z : h2.w;
                float v3 = (kk == 0) ? h3.x : (kk == 1) ? h3.y : (kk == 2) ? h3.z : h3.w;
                acc[0][0] = fmaf(v0, w.x, acc[0][0]);
                acc[0][1] = fmaf(v0, w.y, acc[0][1]);
                acc[1][0] = fmaf(v1, w.x, acc[1][0]);
                acc[1][1] = fmaf(v1, w.y, acc[1][1]);
                acc[2][0] = fmaf(v2, w.x, acc[2][0]);
                acc[2][1] = fmaf(v2, w.y, acc[2][1]);
                acc[3][0] = fmaf(v3, w.x, acc[3][0]);
                acc[3][1] = fmaf(v3, w.y, acc[3][1]);
            }
        }
        __syncthreads();   // all reads of hs done before overwrite
        #pragma unroll
        for (int r = 0; r < 4; r++) {
            const float* xp = &Xp[((long)(b0 + r) * TTOT + t) * NFEAT + n0];
            float v0 = tanhf(xp[0] + acc[r][0]);
            float v1 = tanhf(xp[1] + acc[r][1]);
            hs[r][n0] = v0; hs[r][n0 + 1] = v1;
            float* hp = &Hs[((long)(b0 + r) * TSEQ + t) * NFEAT + n0];
            hp[0] = v0; hp[1] = v1;
        }
        __syncthreads();
    }
}

// ---------------- small prep kernels ----------------
__global__ void init_kernel(const float* __restrict__ b_ih,
                            const float* __restrict__ b_hh,
                            float* __restrict__ bsum) {
    int i = threadIdx.x;
    if (i < NFEAT) bsum[i] = b_ih[i] + b_hh[i];
    if (i < 2) g_loss[i] = 0.0;
}

__global__ void transpose_kernel(const float* __restrict__ W,
                                 float* __restrict__ WT) {
    __shared__ float tile[32][33];
    int x = blockIdx.x * 32 + threadIdx.x;
    int y = blockIdx.y * 32 + threadIdx.y;
    #pragma unroll
    for (int j = 0; j < 32; j += 8)
        tile[threadIdx.y + j][threadIdx.x] = W[(long)(y + j) * NFEAT + x];
    __syncthreads();
    x = blockIdx.y * 32 + threadIdx.x;
    y = blockIdx.x * 32 + threadIdx.y;
    #pragma unroll
    for (int j = 0; j < 32; j += 8)
        WT[(long)(y + j) * NFEAT + x] = tile[threadIdx.x][threadIdx.y + j];
}

__global__ void wcat_kernel(const float* __restrict__ Wih,
                            const float* __restrict__ Whh,
                            float* __restrict__ Wcat) {
    int i = blockIdx.x * 256 + threadIdx.x;
    if (i < 512 * 1024) {
        int n = i >> 10, c = i & 1023;
        Wcat[i] = (c < 512) ? Wih[n * 512 + c] : Whh[n * 512 + (c - 512)];
    }
}

// loss1: sum over (Y[b,t] - x[b,t+1])^2 for t in [0,62]
__global__ void loss1_kernel(const float* __restrict__ Y, const float* __restrict__ x) {
    const long total = (long)BSZ * 63 * NFEAT;
    float local = 0.f;
    for (long e = (long)blockIdx.x * blockDim.x + threadIdx.x; e < total;
         e += (long)gridDim.x * blockDim.x) {
        int f  = (int)(e & 511);
        long bt = e >> 9;
        int tt = (int)(bt % 63);
        int b  = (int)(bt / 63);
        float yv = Y[((long)b * TSEQ + tt) * NFEAT + f];
        float xv = x[((long)b * TTOT + tt + 1) * NFEAT + f];
        float d = yv - xv;
        local += d * d;
    }
    float s = blockReduceSum(local);
    if (threadIdx.x == 0) atomicAdd(&g_loss[0], (double)s);
}

// seed decode state S0 = [Y[:,63,:] | Hs[:,63,:]]
__global__ void seed_kernel(const float* __restrict__ Y,
                            const float* __restrict__ Hs,
                            float* __restrict__ S0) {
    int e = blockIdx.x * 256 + threadIdx.x;
    if (e < BSZ * NFEAT) {
        int b = e >> 9, f = e & 511;
        S0[(long)b * 1024 + f]       = Y [((long)b * TSEQ + (TSEQ - 1)) * NFEAT + f];
        S0[(long)b * 1024 + 512 + f] = Hs[((long)b * TSEQ + (TSEQ - 1)) * NFEAT + f];
    }
}

// gather x_pred = Xg[t[b]-1][b,:], write to out, accumulate loss2
__global__ void final_kernel(const float* __restrict__ Xg, const float* __restrict__ x,
                             const int* __restrict__ t, float* __restrict__ out,
                             int out_size) {
    int e = blockIdx.x * blockDim.x + threadIdx.x;
    float local = 0.f;
    if (e < BSZ * NFEAT) {
        int b = e >> 9, f = e & 511;
        int gp = t[b] - 1;
        float v = Xg[(long)gp * BSZ * NFEAT + e];
        if (e < out_size) out[e] = v;
        float xf = x[((long)b * TTOT + TSEQ) * NFEAT + f];
        float d = v - xf;
        local = d * d;
    }
    float s = blockReduceSum(local);
    if (threadIdx.x == 0) atomicAdd(&g_loss[1], (double)s);
}

__global__ void write_loss_kernel(float* __restrict__ out, int out_size) {
    const double n1 = 16515072.0;  // 63*512*512
    const double n2 = 262144.0;    // 512*512
    double l = g_loss[0] / (n1 * n1) + g_loss[1] / (n2 * n2);
    for (int i = BSZ * NFEAT + threadIdx.x; i < out_size; i += blockDim.x)
        out[i] = (float)l;
}

// ---------------- host launchers ----------------
static inline void gemm_big(const float* A, int lda, const float* W,
                            float* C, int ldc, int M, int N, int K, int mode,
                            const float* bias,
                            const float* g, const float* beta,
                            const float* rm, const float* rv) {
    dim3 grid((N + 127) / 128, (M + 127) / 128);
    gemm_kernel<128, 128, 8, 8, 8, 256><<<grid, 256>>>(
        A, lda, W, C, ldc, nullptr, 0, M, N, K, mode, bias, g, beta, rm, rv);
}

static inline void gemm_small(const float* A, int lda, const float* W,
                              float* C, int ldc, float* C2, int ldc2,
                              int M, int N, int K, int mode,
                              const float* bias,
                              const float* g, const float* beta,
                              const float* rm, const float* rv) {
    dim3 grid((N + 63) / 64, (M + 63) / 64);
    gemm_kernel<64, 64, 16, 4, 4, 256><<<grid, 256>>>(
        A, lda, W, C, ldc, C2, ldc2, M, N, K, mode, bias, g, beta, rm, rv);
}

extern "C" void kernel_launch(void* const* d_in, const int* in_sizes, int n_in,
                              void* d_out, int out_size) {
    const float* x     = (const float*)d_in[0];
    const int*   t     = (const int*)  d_in[1];
    const float* W_ih  = (const float*)d_in[2];
    const float* W_hh  = (const float*)d_in[3];
    const float* b_ih  = (const float*)d_in[4];
    const float* b_hh  = (const float*)d_in[5];
    const float* W1    = (const float*)d_in[6];
    const float* b1    = (const float*)d_in[7];
    const float* g1    = (const float*)d_in[8];
    const float* beta1 = (const float*)d_in[9];
    const float* rm1   = (const float*)d_in[10];
    const float* rv1   = (const float*)d_in[11];
    const float* W2    = (const float*)d_in[12];
    const float* b2    = (const float*)d_in[13];
    const float* g2    = (const float*)d_in[14];
    const float* beta2 = (const float*)d_in[15];
    const float* rm2   = (const float*)d_in[16];
    const float* rv2   = (const float*)d_in[17];
    const float* W3    = (const float*)d_in[18];
    const float* b3    = (const float*)d_in[19];
    const float* g3    = (const float*)d_in[20];
    const float* beta3 = (const float*)d_in[21];
    const float* rm3   = (const float*)d_in[22];
    const float* rv3   = (const float*)d_in[23];
    float* out = (float*)d_out;

    float* buf = nullptr;
    cudaGetSymbolAddress((void**)&buf, g_buf);

    float* Xp   = buf + OFF_XP;
    float* Hs   = buf + OFF_HS;
    float* Z1   = buf + OFF_Z1;
    float* Z2   = buf + OFF_Z2;
    float* Y    = buf + OFF_Y;     // aliases Z1 (dead by then)
    float* WT   = buf + OFF_WT;
    float* Wcat = buf + OFF_WC;
    float* bsum = buf + OFF_BS;

    // decode scratch (overlays Xp; Xp dead after scan)
    float* S0   = buf + DOFF_S0;
    float* S1   = buf + DOFF_S1;
    float* Z1d  = buf + DOFF_Z1D;
    float* Z2d  = buf + DOFF_Z2D;
    float* Xg   = buf + DOFF_XG;

    // 0. prep: bsum, loss zero, W_hh^T, W_cat
    init_kernel<<<1, 512>>>(b_ih, b_hh, bsum);
    transpose_kernel<<<dim3(16, 16), dim3(32, 8)>>>(W_hh, WT);
    wcat_kernel<<<(512 * 1024 + 255) / 256, 256>>>(W_ih, W_hh, Wcat);

    // 1. Xp = x @ W_ih^T + bsum  (all 65 timesteps)
    gemm_big(x, NFEAT, W_ih, Xp, NFEAT, BSZ * TTOT, NFEAT, NFEAT,
             0, bsum, nullptr, nullptr, nullptr, nullptr);

    // 2+3. full RNN scan in ONE persistent kernel (batch-parallel)
    scan_kernel<<<BSZ / 4, 256>>>(Xp, WT, Hs);

    // 4. autoencoder on all B*T rows (Z1 -> Z2 -> Y, Y aliases Z1)
    gemm_big(Hs, NFEAT, W1, Z1, HID, BSZ * TSEQ, HID, NFEAT,
             2, b1, g1, beta1, rm1, rv1);
    gemm_big(Z1, HID, W2, Z2, HID, BSZ * TSEQ, HID, HID,
             2, b2, g2, beta2, rm2, rv2);
    gemm_big(Z2, HID, W3, Y, NFEAT, BSZ * TSEQ, NFEAT, HID,
             2, b3, g3, beta3, rm3, rv3);

    // 5. loss1 + decode seed (S0 = [y_63 | h_63]); safe: S0 overlays Xp only
    loss1_kernel<<<2048, 256>>>(Y, x);
    seed_kernel<<<(BSZ * NFEAT + 255) / 256, 256>>>(Y, Hs, S0);

    // 6. decode loop: 16 steps x 4 GEMMs
    for (int g = 0; g < NGAP; g++) {
        float* Sin  = (g & 1) ? S1 : S0;
        float* Sout = (g & 1) ? S0 : S1;
        // h' = tanh([x|h] @ Wcat^T + bsum)  -> Sout cols 512..1023
        gemm_small(Sin, 1024, Wcat, Sout + 512, 1024, nullptr, 0,
                   BSZ, NFEAT, 1024, 3, bsum, nullptr, nullptr, nullptr, nullptr);
        // autoencoder; last layer dual-writes Xg[g] and Sout x-part
        gemm_small(Sout + 512, 1024, W1, Z1d, HID, nullptr, 0,
                   BSZ, HID, NFEAT, 2, b1, g1, beta1, rm1, rv1);
        gemm_small(Z1d, HID, W2, Z2d, HID, nullptr, 0,
                   BSZ, HID, HID, 2, b2, g2, beta2, rm2, rv2);
        gemm_small(Z2d, HID, W3, Xg + (long)g * BSZ * NFEAT, NFEAT, Sout, 1024,
                   BSZ, NFEAT, HID, 2, b3, g3, beta3, rm3, rv3);
    }

    // 7. gather x_pred, loss2
    final_kernel<<<(BSZ * NFEAT + 255) / 256, 256>>>(Xg, x, t, out, out_size);

    // 8. final loss
    write_loss_kernel<<<1, 256>>>(out, out_size);
}

// round 5
// speedup vs baseline: 1.3658x; 1.2019x over previous
#include <cuda_runtime.h>
#include <mma.h>
#include <math.h>

using namespace nvcuda;

#define BSZ   512
#define NFEAT 512
#define HID   1000
#define HIDP  1024
#define TTOT  65
#define TSEQ  64
#define NGAP  16
#define NCHUNK 4
#define MCH   (BSZ * TSEQ / NCHUNK)   // 8192 rows per autoenc chunk

// ---------------- scratch layout ----------------
#define SZ_XP   (512L*65*512)          // 17,039,360
#define SZ_HS   (512L*64*512)          // 16,777,216
#define SZ_Z    (8192L*1024)           //  8,388,608 (per chunk)
#define SZ_Y    (512L*64*512)          // 16,777,216

#define OFF_XP  0L
#define OFF_HS  (OFF_XP+SZ_XP)
#define OFF_Z1  (OFF_HS+SZ_HS)
#define OFF_Z2  (OFF_Z1+SZ_Z)
#define OFF_Y   (OFF_Z2+SZ_Z)
#define OFF_W1P (OFF_Y+SZ_Y)           // 1024 x 512
#define OFF_W2P (OFF_W1P+1024L*512)    // 1024 x 1024
#define OFF_W3P (OFF_W2P+1024L*1024)   // 512 x 1024
#define OFF_WC  (OFF_W3P+512L*1024)    // 512 x 1024
#define OFF_WT  (OFF_WC+512L*1024)     // 512 x 512
#define OFF_P1  (OFF_WT+512L*512)      // 5 x 1024
#define OFF_P2  (OFF_P1+5L*1024)       // 5 x 1024
#define OFF_BS  (OFF_P2+5L*1024)       // 512
#define TOTAL_BUF (OFF_BS+512L)

// decode-phase scratch overlays Xp (dead after scan)
#define DOFF_S0   0L
#define DOFF_S1   (DOFF_S0 + 512L*1024)
#define DOFF_Z1D  (DOFF_S1 + 512L*1024)
#define DOFF_Z2D  (DOFF_Z1D + 512L*1024)
#define DOFF_XG   (DOFF_Z2D + 512L*1024)   // 16 x 512 x 512

__device__ float  g_buf[TOTAL_BUF];
__device__ double g_loss[2];

// ---------------- reductions ----------------
__inline__ __device__ float blockReduceSum(float v) {
    __shared__ float s[32];
    int lane = threadIdx.x & 31;
    int wid  = threadIdx.x >> 5;
    #pragma unroll
    for (int o = 16; o > 0; o >>= 1) v += __shfl_down_sync(0xffffffffu, v, o);
    if (lane == 0) s[wid] = v;
    __syncthreads();
    int nwarp = blockDim.x >> 5;
    v = (threadIdx.x < nwarp) ? s[lane] : 0.f;
    if (wid == 0) {
        #pragma unroll
        for (int o = 16; o > 0; o >>= 1) v += __shfl_down_sync(0xffffffffu, v, o);
    }
    return v;
}

// ---------------- tf32 tensor-core GEMM: C = epi(A @ W^T) ----------------
// A: M x K (row stride lda). W: N x K rows (row stride ldw). C: M x N (ldc).
// ALL of M,N,K must be exact multiples of BM,BN,BK (guaranteed by padding).
// mode 0: C = acc + bias[n]
// mode 2: C = (acc + bias[n] - rm[n]) * (g[n]*rsqrt(rv[n]+eps)) + beta[n]
// mode 3: C = tanh(acc + bias[n])
// C2 optional second destination (ldc2).
template<int BM, int BN, int BK, int WM, int WN>
__global__ void __launch_bounds__(256)
tf32_gemm(const float* __restrict__ A, int lda,
          const float* __restrict__ W, int ldw,
          float* __restrict__ C, int ldc,
          float* __restrict__ C2, int ldc2,
          int M, int N, int K, int mode,
          const float* __restrict__ bias,
          const float* __restrict__ gsc, const float* __restrict__ beta,
          const float* __restrict__ rm,  const float* __restrict__ rv)
{
    constexpr int PAD  = 8;
    constexpr int LDS_ = BK + PAD;
    __shared__ __align__(16) float As[BM][LDS_];
    __shared__ __align__(16) float Ws[BN][LDS_];

    const int tid    = threadIdx.x;
    const int bm     = blockIdx.y * BM;
    const int bn     = blockIdx.x * BN;
    const int warpId = tid >> 5;
    const int lane   = tid & 31;

    constexpr int NWN = BN / WN;
    const int wm = warpId / NWN;
    const int wn = warpId % NWN;
    constexpr int TMI = WM / 16;
    constexpr int TNI = WN / 16;

    wmma::fragment<wmma::accumulator, 16, 16, 8, float> acc[TMI][TNI];
    #pragma unroll
    for (int i = 0; i < TMI; i++)
        #pragma unroll
        for (int j = 0; j < TNI; j++)
            wmma::fill_fragment(acc[i][j], 0.0f);

    constexpr int A4 = BM * BK / (256 * 4);
    constexpr int W4 = BN * BK / (256 * 4);

    for (int k0 = 0; k0 < K; k0 += BK) {
        #pragma unroll
        for (int l = 0; l < A4; l++) {
            int idx = (tid + l * 256) * 4;
            int r = idx / BK, c = idx % BK;
            float4 v = *reinterpret_cast<const float4*>(A + (long)(bm + r) * lda + k0 + c);
            *reinterpret_cast<float4*>(&As[r][c]) = v;
        }
        #pragma unroll
        for (int l = 0; l < W4; l++) {
            int idx = (tid + l * 256) * 4;
            int r = idx / BK, c = idx % BK;
            float4 v = *reinterpret_cast<const float4*>(W + (long)(bn + r) * ldw + k0 + c);
            *reinterpret_cast<float4*>(&Ws[r][c]) = v;
        }
        __syncthreads();

        #pragma unroll
        for (int kk = 0; kk < BK; kk += 8) {
            wmma::fragment<wmma::matrix_a, 16, 16, 8, wmma::precision::tf32, wmma::row_major> af[TMI];
            wmma::fragment<wmma::matrix_b, 16, 16, 8, wmma::precision::tf32, wmma::col_major> bf[TNI];
            #pragma unroll
            for (int i = 0; i < TMI; i++) {
                wmma::load_matrix_sync(af[i], &As[wm * WM + i * 16][kk], LDS_);
                #pragma unroll
                for (int e = 0; e < af[i].num_elements; e++)
                    af[i].x[e] = wmma::__float_to_tf32(af[i].x[e]);
            }
            #pragma unroll
            for (int j = 0; j < TNI; j++) {
                wmma::load_matrix_sync(bf[j], &Ws[wn * WN + j * 16][kk], LDS_);
                #pragma unroll
                for (int e = 0; e < bf[j].num_elements; e++)
                    bf[j].x[e] = wmma::__float_to_tf32(bf[j].x[e]);
            }
            #pragma unroll
            for (int i = 0; i < TMI; i++)
                #pragma unroll
                for (int j = 0; j < TNI; j++)
                    wmma::mma_sync(acc[i][j], af[i], bf[j], acc[i][j]);
        }
        __syncthreads();
    }

    // epilogue via per-warp smem staging (reuses As storage)
    float* stage = &As[0][0] + warpId * 256;
    #pragma unroll
    for (int i = 0; i < TMI; i++) {
        #pragma unroll
        for (int j = 0; j < TNI; j++) {
            wmma::store_matrix_sync(stage, acc[i][j], 16, wmma::mem_row_major);
            __syncwarp();
            int r  = lane >> 1;
            int cb = (lane & 1) * 8;
            const float* sp = stage + r * 16 + cb;
            int gm  = bm + wm * WM + i * 16 + r;
            int gn0 = bn + wn * WN + j * 16 + cb;
            float v[8];
            #pragma unroll
            for (int q = 0; q < 8; q++) {
                int n = gn0 + q;
                float a = sp[q];
                if (mode == 0)      v[q] = a + bias[n];
                else if (mode == 3) v[q] = tanhf(a + bias[n]);
                else                v[q] = (a + bias[n] - rm[n]) *
                                           (gsc[n] * rsqrtf(rv[n] + 1e-5f)) + beta[n];
            }
            float4* cp = reinterpret_cast<float4*>(C + (long)gm * ldc + gn0);
            cp[0] = make_float4(v[0], v[1], v[2], v[3]);
            cp[1] = make_float4(v[4], v[5], v[6], v[7]);
            if (C2) {
                float4* cp2 = reinterpret_cast<float4*>(C2 + (long)gm * ldc2 + gn0);
                cp2[0] = make_float4(v[0], v[1], v[2], v[3]);
                cp2[1] = make_float4(v[4], v[5], v[6], v[7]);
            }
            __syncwarp();
        }
    }
}

// ---------------- persistent RNN scan (fp32, batch-parallel) ----------------
__global__ void __launch_bounds__(256)
scan_kernel(const float* __restrict__ Xp, const float* __restrict__ WT,
            float* __restrict__ Hs)
{
    __shared__ __align__(16) float hs[4][NFEAT];
    const int tid = threadIdx.x;
    const int b0 = blockIdx.x * 4;
    const int n0 = tid * 2;

    for (int i = tid; i < 4 * NFEAT; i += 256) {
        int r = i >> 9, f = i & 511;
        float v = tanhf(Xp[((long)(b0 + r) * TTOT) * NFEAT + f]);
        hs[r][f] = v;
        Hs[((long)(b0 + r) * TSEQ) * NFEAT + f] = v;
    }
    __syncthreads();

    for (int t = 1; t < TSEQ; t++) {
        float acc[4][2];
        #pragma unroll
        for (int r = 0; r < 4; r++) { acc[r][0] = 0.f; acc[r][1] = 0.f; }

        #pragma unroll 4
        for (int k = 0; k < NFEAT; k += 4) {
            float4 h0 = *reinterpret_cast<const float4*>(&hs[0][k]);
            float4 h1 = *reinterpret_cast<const float4*>(&hs[1][k]);
            float4 h2 = *reinterpret_cast<const float4*>(&hs[2][k]);
            float4 h3 = *reinterpret_cast<const float4*>(&hs[3][k]);
            #pragma unroll
            for (int kk = 0; kk < 4; kk++) {
                float2 w = *reinterpret_cast<const float2*>(
                    &WT[(long)(k + kk) * NFEAT + n0]);
                float v0 = (kk == 0) ? h0.x : (kk == 1) ? h0.y : (kk == 2) ? h0.z : h0.w;
                float v1 = (kk == 0) ? h1.x : (kk == 1) ? h1.y : (kk == 2) ? h1.z : h1.w;
                float v2 = (kk == 0) ? h2.x : (kk == 1) ? h2.y : (kk == 2) ? h2.z : h2.w;
                float v3 = (kk == 0) ? h3.x : (kk == 1) ? h3.y : (kk == 2) ? h3.z : h3.w;
                acc[0][0] = fmaf(v0, w.x, acc[0][0]);
                acc[0][1] = fmaf(v0, w.y, acc[0][1]);
                acc[1][0] = fmaf(v1, w.x, acc[1][0]);
                acc[1][1] = fmaf(v1, w.y, acc[1][1]);
                acc[2][0] = fmaf(v2, w.x, acc[2][0]);
                acc[2][1] = fmaf(v2, w.y, acc[2][1]);
                acc[3][0] = fmaf(v3, w.x, acc[3][0]);
                acc[3][1] = fmaf(v3, w.y, acc[3][1]);
            }
        }
        __syncthreads();
        #pragma unroll
        for (int r = 0; r < 4; r++) {
            const float* xp = &Xp[((long)(b0 + r) * TTOT + t) * NFEAT + n0];
            float v0 = tanhf(xp[0] + acc[r][0]);
            float v1 = tanhf(xp[1] + acc[r][1]);
            hs[r][n0] = v0; hs[r][n0 + 1] = v1;
            float* hp = &Hs[((long)(b0 + r) * TSEQ + t) * NFEAT + n0];
            hp[0] = v0; hp[1] = v1;
        }
        __syncthreads();
    }
}

// ---------------- prep kernels ----------------
__global__ void init_kernel(const float* __restrict__ b_ih,
                            const float* __restrict__ b_hh,
                            float* __restrict__ bsum) {
    int i = threadIdx.x;
    if (i < NFEAT) bsum[i] = b_ih[i] + b_hh[i];
    if (i < 2) g_loss[i] = 0.0;
}

__global__ void transpose_kernel(const float* __restrict__ W,
                                 float* __restrict__ WT) {
    __shared__ float tile[32][33];
    int x = blockIdx.x * 32 + threadIdx.x;
    int y = blockIdx.y * 32 + threadIdx.y;
    #pragma unroll
    for (int j = 0; j < 32; j += 8)
        tile[threadIdx.y + j][threadIdx.x] = W[(long)(y + j) * NFEAT + x];
    __syncthreads();
    x = blockIdx.y * 32 + threadIdx.x;
    y = blockIdx.x * 32 + threadIdx.y;
    #pragma unroll
    for (int j = 0; j < 32; j += 8)
        WT[(long)(y + j) * NFEAT + x] = tile[threadIdx.x][threadIdx.y + j];
}

__global__ void wcat_kernel(const float* __restrict__ Wih,
                            const float* __restrict__ Whh,
                            float* __restrict__ Wcat) {
    int i = blockIdx.x * 256 + threadIdx.x;
    if (i < 512 * 1024) {
        int n = i >> 10, c = i & 1023;
        Wcat[i] = (c < 512) ? Wih[n * 512 + c] : Whh[n * 512 + (c - 512)];
    }
}

__global__ void pad_w1(const float* __restrict__ W1, float* __restrict__ W1p) {
    int i = blockIdx.x * 256 + threadIdx.x;
    if (i < HIDP * 512) { int n = i >> 9, k = i & 511;
        W1p[i] = (n < HID) ? W1[n * 512 + k] : 0.f; }
}
__global__ void pad_w2(const float* __restrict__ W2, float* __restrict__ W2p) {
    int i = blockIdx.x * 256 + threadIdx.x;
    if (i < HIDP * HIDP) { int n = i >> 10, k = i & 1023;
        W2p[i] = (n < HID && k < HID) ? W2[n * HID + k] : 0.f; }
}
__global__ void pad_w3(const float* __restrict__ W3, float* __restrict__ W3p) {
    int i = blockIdx.x * 256 + threadIdx.x;
    if (i < 512 * HIDP) { int n = i >> 10, k = i & 1023;
        W3p[i] = (k < HID) ? W3[n * HID + k] : 0.f; }
}
__global__ void pad_params(const float* __restrict__ b, const float* __restrict__ g,
                           const float* __restrict__ be, const float* __restrict__ rm,
                           const float* __restrict__ rv, float* __restrict__ dst) {
    int i = blockIdx.x * 256 + threadIdx.x;
    if (i < HIDP) {
        bool v = i < HID;
        dst[i]            = v ? b[i]  : 0.f;
        dst[HIDP + i]     = v ? g[i]  : 0.f;
        dst[2 * HIDP + i] = v ? be[i] : 0.f;
        dst[3 * HIDP + i] = v ? rm[i] : 0.f;
        dst[4 * HIDP + i] = v ? rv[i] : 1.f;
    }
}

// ---------------- loss / gather kernels ----------------
__global__ void loss1_kernel(const float* __restrict__ Y, const float* __restrict__ x) {
    const long total = (long)BSZ * 63 * NFEAT;
    float local = 0.f;
    for (long e = (long)blockIdx.x * blockDim.x + threadIdx.x; e < total;
         e += (long)gridDim.x * blockDim.x) {
        int f  = (int)(e & 511);
        long bt = e >> 9;
        int tt = (int)(bt % 63);
        int b  = (int)(bt / 63);
        float yv = Y[((long)b * TSEQ + tt) * NFEAT + f];
        float xv = x[((long)b * TTOT + tt + 1) * NFEAT + f];
        float d = yv - xv;
        local += d * d;
    }
    float s = blockReduceSum(local);
    if (threadIdx.x == 0) atomicAdd(&g_loss[0], (double)s);
}

__global__ void seed_kernel(const float* __restrict__ Y,
                            const float* __restrict__ Hs,
                            float* __restrict__ S0) {
    int e = blockIdx.x * 256 + threadIdx.x;
    if (e < BSZ * NFEAT) {
        int b = e >> 9, f = e & 511;
        S0[(long)b * 1024 + f]       = Y [((long)b * TSEQ + (TSEQ - 1)) * NFEAT + f];
        S0[(long)b * 1024 + 512 + f] = Hs[((long)b * TSEQ + (TSEQ - 1)) * NFEAT + f];
    }
}

__global__ void final_kernel(const float* __restrict__ Xg, const float* __restrict__ x,
                             const int* __restrict__ t, float* __restrict__ out,
                             int out_size) {
    int e = blockIdx.x * blockDim.x + threadIdx.x;
    float local = 0.f;
    if (e < BSZ * NFEAT) {
        int b = e >> 9, f = e & 511;
        int gp = t[b] - 1;
        float v = Xg[(long)gp * BSZ * NFEAT + e];
        if (e < out_size) out[e] = v;
        float xf = x[((long)b * TTOT + TSEQ) * NFEAT + f];
        float d = v - xf;
        local = d * d;
    }
    float s = blockReduceSum(local);
    if (threadIdx.x == 0) atomicAdd(&g_loss[1], (double)s);
}

__global__ void write_loss_kernel(float* __restrict__ out, int out_size) {
    const double n1 = 16515072.0;  // 63*512*512
    const double n2 = 262144.0;    // 512*512
    double l = g_loss[0] / (n1 * n1) + g_loss[1] / (n2 * n2);
    for (int i = BSZ * NFEAT + threadIdx.x; i < out_size; i += blockDim.x)
        out[i] = (float)l;
}

// ---------------- host launchers ----------------
static inline void gemm128(const float* A, int lda, const float* W, int ldw,
                           float* C, int ldc, int M, int N, int K, int mode,
                           const float* bias, const float* g, const float* be,
                           const float* rm, const float* rv) {
    dim3 grid(N / 128, M / 128);
    tf32_gemm<128, 128, 32, 32, 64><<<grid, 256>>>(
        A, lda, W, ldw, C, ldc, nullptr, 0, M, N, K, mode, bias, g, be, rm, rv);
}

static inline void gemm64(const float* A, int lda, const float* W, int ldw,
                          float* C, int ldc, float* C2, int ldc2,
                          int M, int N, int K, int mode,
                          const float* bias, const float* g, const float* be,
                          const float* rm, const float* rv) {
    dim3 grid(N / 128, M / 64);
    tf32_gemm<64, 128, 32, 32, 32><<<grid, 256>>>(
        A, lda, W, ldw, C, ldc, C2, ldc2, M, N, K, mode, bias, g, be, rm, rv);
}

extern "C" void kernel_launch(void* const* d_in, const int* in_sizes, int n_in,
                              void* d_out, int out_size) {
    const float* x     = (const float*)d_in[0];
    const int*   t     = (const int*)  d_in[1];
    const float* W_ih  = (const float*)d_in[2];
    const float* W_hh  = (const float*)d_in[3];
    const float* b_ih  = (const float*)d_in[4];
    const float* b_hh  = (const float*)d_in[5];
    const float* W1    = (const float*)d_in[6];
    const float* b1    = (const float*)d_in[7];
    const float* g1    = (const float*)d_in[8];
    const float* beta1 = (const float*)d_in[9];
    const float* rm1   = (const float*)d_in[10];
    const float* rv1   = (const float*)d_in[11];
    const float* W2    = (const float*)d_in[12];
    const float* b2    = (const float*)d_in[13];
    const float* g2    = (const float*)d_in[14];
    const float* beta2 = (const float*)d_in[15];
    const float* rm2   = (const float*)d_in[16];
    const float* rv2   = (const float*)d_in[17];
    const float* W3    = (const float*)d_in[18];
    const float* b3    = (const float*)d_in[19];
    const float* g3    = (const float*)d_in[20];
    const float* beta3 = (const float*)d_in[21];
    const float* rm3   = (const float*)d_in[22];
    const float* rv3   = (const float*)d_in[23];
    float* out = (float*)d_out;

    float* buf = nullptr;
    cudaGetSymbolAddress((void**)&buf, g_buf);

    float* Xp   = buf + OFF_XP;
    float* Hs   = buf + OFF_HS;
    float* Z1   = buf + OFF_Z1;
    float* Z2   = buf + OFF_Z2;
    float* Y    = buf + OFF_Y;
    float* W1p  = buf + OFF_W1P;
    float* W2p  = buf + OFF_W2P;
    float* W3p  = buf + OFF_W3P;
    float* Wcat = buf + OFF_WC;
    float* WT   = buf + OFF_WT;
    float* P1   = buf + OFF_P1;
    float* P2   = buf + OFF_P2;
    float* bsum = buf + OFF_BS;

    // padded params: [b | g | beta | rm | rv] x 1024
    float *b1p = P1, *g1p = P1 + HIDP, *be1p = P1 + 2*HIDP, *rm1p = P1 + 3*HIDP, *rv1p = P1 + 4*HIDP;
    float *b2p = P2, *g2p = P2 + HIDP, *be2p = P2 + 2*HIDP, *rm2p = P2 + 3*HIDP, *rv2p = P2 + 4*HIDP;

    // decode scratch (overlays Xp; Xp dead after scan)
    float* S0  = buf + DOFF_S0;
    float* S1  = buf + DOFF_S1;
    float* Z1d = buf + DOFF_Z1D;
    float* Z2d = buf + DOFF_Z2D;
    float* Xg  = buf + DOFF_XG;

    // 0. prep
    init_kernel<<<1, 512>>>(b_ih, b_hh, bsum);
    transpose_kernel<<<dim3(16, 16), dim3(32, 8)>>>(W_hh, WT);
    wcat_kernel<<<(512 * 1024 + 255) / 256, 256>>>(W_ih, W_hh, Wcat);
    pad_w1<<<(HIDP * 512 + 255) / 256, 256>>>(W1, W1p);
    pad_w2<<<(HIDP * HIDP + 255) / 256, 256>>>(W2, W2p);
    pad_w3<<<(512 * HIDP + 255) / 256, 256>>>(W3, W3p);
    pad_params<<<(HIDP + 255) / 256, 256>>>(b1, g1, beta1, rm1, rv1, P1);
    pad_params<<<(HIDP + 255) / 256, 256>>>(b2, g2, beta2, rm2, rv2, P2);

    // 1. Xp = x @ W_ih^T + bsum  (M = 512*65 = 33280)
    gemm128(x, NFEAT, W_ih, NFEAT, Xp, NFEAT, BSZ * TTOT, NFEAT, NFEAT,
            0, bsum, nullptr, nullptr, nullptr, nullptr);

    // 2+3. full RNN scan in one persistent kernel
    scan_kernel<<<BSZ / 4, 256>>>(Xp, WT, Hs);

    // 4. autoencoder on all B*T rows, chunked over M to bound scratch
    for (int c = 0; c < NCHUNK; c++) {
        const float* Ac = Hs + (long)c * MCH * NFEAT;
        float*       Yc = Y  + (long)c * MCH * NFEAT;
        gemm128(Ac, NFEAT, W1p, NFEAT, Z1, HIDP, MCH, HIDP, NFEAT,
                2, b1p, g1p, be1p, rm1p, rv1p);
        gemm128(Z1, HIDP, W2p, HIDP, Z2, HIDP, MCH, HIDP, HIDP,
                2, b2p, g2p, be2p, rm2p, rv2p);
        gemm128(Z2, HIDP, W3p, HIDP, Yc, NFEAT, MCH, NFEAT, HIDP,
                2, b3, g3, beta3, rm3, rv3);
    }

    // 5. loss1 + decode seed
    loss1_kernel<<<2048, 256>>>(Y, x);
    seed_kernel<<<(BSZ * NFEAT + 255) / 256, 256>>>(Y, Hs, S0);

    // 6. decode loop: 16 steps x 4 tensor GEMMs
    for (int g = 0; g < NGAP; g++) {
        float* Sin  = (g & 1) ? S1 : S0;
        float* Sout = (g & 1) ? S0 : S1;
        // h' = tanh([x|h] @ Wcat^T + bsum) -> Sout cols 512..1023
        gemm64(Sin, 1024, Wcat, 1024, Sout + 512, 1024, nullptr, 0,
               BSZ, NFEAT, 1024, 3, bsum, nullptr, nullptr, nullptr, nullptr);
        gemm64(Sout + 512, 1024, W1p, NFEAT, Z1d, HIDP, nullptr, 0,
               BSZ, HIDP, NFEAT, 2, b1p, g1p, be1p, rm1p, rv1p);
        gemm64(Z1d, HIDP, W2p, HIDP, Z2d, HIDP, nullptr, 0,
               BSZ, HIDP, HIDP, 2, b2p, g2p, be2p, rm2p, rv2p);
        gemm64(Z2d, HIDP, W3p, HIDP, Xg + (long)g * BSZ * NFEAT, NFEAT, Sout, 1024,
               BSZ, NFEAT, HIDP, 2, b3, g3, beta3, rm3, rv3);
    }

    // 7. gather x_pred, loss2
    final_kernel<<<(BSZ * NFEAT + 255) / 256, 256>>>(Xg, x, t, out, out_size);

    // 8. final loss
    write_loss_kernel<<<1, 256>>>(out, out_size);
}

// round 11
// speedup vs baseline: 1.6183x; 1.1848x over previous
#include <cuda_runtime.h>
#include <mma.h>
#include <math.h>
#include <stdint.h>
#include <cstdint>

using namespace nvcuda;

#define BSZ   512
#define NFEAT 512
#define HID   1000
#define HIDP  1024
#define TTOT  65
#define TSEQ  64
#define NGAP  16
#define NCHUNK 4
#define MCH   (BSZ * TSEQ / NCHUNK)   // 8192 rows per autoenc chunk

// ---------------- scratch layout ----------------
#define SZ_XP   (512L*65*512)
#define SZ_HS   (512L*64*512)
#define SZ_Z    (8192L*1024)
#define SZ_Y    (512L*64*512)

#define OFF_XP  0L
#define OFF_HS  (OFF_XP+SZ_XP)
#define OFF_Z1  (OFF_HS+SZ_HS)
#define OFF_Z2  (OFF_Z1+SZ_Z)
#define OFF_Y   (OFF_Z2+SZ_Z)
#define OFF_W1P (OFF_Y+SZ_Y)           // 1024 x 512   (tf32-rounded)
#define OFF_W2P (OFF_W1P+1024L*512)    // 1024 x 1024  (tf32-rounded)
#define OFF_W3P (OFF_W2P+1024L*1024)   // 512 x 1024   (tf32-rounded)
#define OFF_WC  (OFF_W3P+512L*1024)    // 512 x 1024   (tf32-rounded)
#define OFF_WT  (OFF_WC+512L*1024)     // 512 x 512    (full fp32, scan)
#define OFF_P1  (OFF_WT+512L*512)      // 5 x 1024
#define OFF_P2  (OFF_P1+5L*1024)
#define OFF_BS  (OFF_P2+5L*1024)       // 512
#define OFF_WIR (OFF_BS+512L)          // 512 x 512    (W_ih tf32-rounded)
#define TOTAL_BUF (OFF_WIR+512L*512)

// decode-phase scratch overlays Xp (dead after scan)
#define DOFF_S0   0L
#define DOFF_S1   (DOFF_S0 + 512L*1024)
#define DOFF_Z1D  (DOFF_S1 + 512L*1024)
#define DOFF_Z2D  (DOFF_Z1D + 512L*1024)
#define DOFF_XG   (DOFF_Z2D + 512L*1024)

__device__ float  g_buf[TOTAL_BUF];
__device__ double g_loss[2];

// ---------------- helpers ----------------
__device__ __forceinline__ float rnd_tf32(float x) {
    float y;
    asm("cvt.rna.tf32.f32 %0, %1;" : "=f"(y) : "f"(x));
    return y;
}
__device__ __forceinline__ void cp_async16(unsigned int s, const float* g) {
    asm volatile("cp.async.cg.shared.global [%0], [%1], 16;\n" :: "r"(s), "l"(g));
}
__device__ __forceinline__ void cp_commit() {
    asm volatile("cp.async.commit_group;\n" ::);
}
template<int N> __device__ __forceinline__ void cp_wait() {
    asm volatile("cp.async.wait_group %0;\n" :: "n"(N));
}

__inline__ __device__ float blockReduceSum(float v) {
    __shared__ float s[32];
    int lane = threadIdx.x & 31;
    int wid  = threadIdx.x >> 5;
    #pragma unroll
    for (int o = 16; o > 0; o >>= 1) v += __shfl_down_sync(0xffffffffu, v, o);
    if (lane == 0) s[wid] = v;
    __syncthreads();
    int nwarp = blockDim.x >> 5;
    v = (threadIdx.x < nwarp) ? s[lane] : 0.f;
    if (wid == 0) {
        #pragma unroll
        for (int o = 16; o > 0; o >>= 1) v += __shfl_down_sync(0xffffffffu, v, o);
    }
    return v;
}

// ---------------- pipelined tf32 tensor GEMM: C = epi(A @ W^T) ----------------
// W rows MUST be pre-rounded to tf32. A is cvt'd per-fragment.
// M,N,K exact multiples of BM,BN,BK. 2-stage cp.async pipeline.
// mode 0: +bias ; mode 2: batchnorm ; mode 3: tanh(+bias). C2 optional.
template<int BM, int BN, int BK, int WM, int WN>
__global__ void __launch_bounds__(256)
tf32_gemm(const float* __restrict__ A, int lda,
          const float* __restrict__ W, int ldw,
          float* __restrict__ C, int ldc,
          float* __restrict__ C2, int ldc2,
          int M, int N, int K, int mode,
          const float* __restrict__ bias,
          const float* __restrict__ gsc, const float* __restrict__ beta,
          const float* __restrict__ rm,  const float* __restrict__ rv)
{
    constexpr int LDS_ = BK + 8;
    extern __shared__ float smem[];
    float* AsBase = smem;                       // 2 * BM * LDS_
    float* WsBase = smem + 2 * BM * LDS_;       // 2 * BN * LDS_

    const int tid    = threadIdx.x;
    const int bm     = blockIdx.y * BM;
    const int bn     = blockIdx.x * BN;
    const int warpId = tid >> 5;
    const int lane   = tid & 31;

    constexpr int NWN = BN / WN;
    const int wm = warpId / NWN;
    const int wn = warpId % NWN;
    constexpr int TMI = WM / 16;
    constexpr int TNI = WN / 16;

    wmma::fragment<wmma::accumulator, 16, 16, 8, float> acc[TMI][TNI];
    #pragma unroll
    for (int i = 0; i < TMI; i++)
        #pragma unroll
        for (int j = 0; j < TNI; j++)
            wmma::fill_fragment(acc[i][j], 0.0f);

    constexpr int CPR = BK / 4;                // 16B chunks per row
    constexpr int ACH = BM * CPR / 256;        // chunks per thread (A)
    constexpr int WCH = BN * CPR / 256;        // chunks per thread (W)

    auto loadA = [&](int st, int k0) {
        #pragma unroll
        for (int l = 0; l < ACH; l++) {
            int c = tid + l * 256;
            int r = c / CPR, col = (c % CPR) * 4;
            unsigned int s = (unsigned int)__cvta_generic_to_shared(
                &AsBase[(st * BM + r) * LDS_ + col]);
            cp_async16(s, A + (long)(bm + r) * lda + k0 + col);
        }
    };
    auto loadW = [&](int st, int k0) {
        #pragma unroll
        for (int l = 0; l < WCH; l++) {
            int c = tid + l * 256;
            int r = c / CPR, col = (c % CPR) * 4;
            unsigned int s = (unsigned int)__cvta_generic_to_shared(
                &WsBase[(st * BN + r) * LDS_ + col]);
            cp_async16(s, W + (long)(bn + r) * ldw + k0 + col);
        }
    };

    const int KT = K / BK;
    loadA(0, 0); loadW(0, 0); cp_commit();

    for (int kt = 0; kt < KT; kt++) {
        int st = kt & 1;
        if (kt + 1 < KT) {
            loadA(st ^ 1, (kt + 1) * BK);
            loadW(st ^ 1, (kt + 1) * BK);
            cp_commit();
            cp_wait<1>();
        } else {
            cp_wait<0>();
        }
        __syncthreads();

        const float* Ast = &AsBase[(st * BM) * LDS_];
        const float* Wst = &WsBase[(st * BN) * LDS_];
        #pragma unroll
        for (int kk = 0; kk < BK; kk += 8) {
            wmma::fragment<wmma::matrix_a, 16, 16, 8, wmma::precision::tf32, wmma::row_major> af[TMI];
            wmma::fragment<wmma::matrix_b, 16, 16, 8, wmma::precision::tf32, wmma::col_major> bf[TNI];
            #pragma unroll
            for (int i = 0; i < TMI; i++) {
                wmma::load_matrix_sync(af[i], Ast + (wm * WM + i * 16) * LDS_ + kk, LDS_);
                #pragma unroll
                for (int e = 0; e < af[i].num_elements; e++)
                    af[i].x[e] = wmma::__float_to_tf32(af[i].x[e]);
            }
            #pragma unroll
            for (int j = 0; j < TNI; j++)
                wmma::load_matrix_sync(bf[j], Wst + (wn * WN + j * 16) * LDS_ + kk, LDS_);
            #pragma unroll
            for (int i = 0; i < TMI; i++)
                #pragma unroll
                for (int j = 0; j < TNI; j++)
                    wmma::mma_sync(acc[i][j], af[i], bf[j], acc[i][j]);
        }
        __syncthreads();
    }

    // epilogue via per-warp smem staging (reuses smem)
    float* stage = smem + warpId * 256;
    #pragma unroll
    for (int i = 0; i < TMI; i++) {
        #pragma unroll
        for (int j = 0; j < TNI; j++) {
            wmma::store_matrix_sync(stage, acc[i][j], 16, wmma::mem_row_major);
            __syncwarp();
            int r  = lane >> 1;
            int cb = (lane & 1) * 8;
            const float* sp = stage + r * 16 + cb;
            int gm  = bm + wm * WM + i * 16 + r;
            int gn0 = bn + wn * WN + j * 16 + cb;
            float v[8];
            #pragma unroll
            for (int q = 0; q < 8; q++) {
                int n = gn0 + q;
                float a = sp[q];
                if (mode == 0)      v[q] = a + bias[n];
                else if (mode == 3) v[q] = tanhf(a + bias[n]);
                else                v[q] = (a + bias[n] - rm[n]) *
                                           (gsc[n] * rsqrtf(rv[n] + 1e-5f)) + beta[n];
            }
            float4* cp = reinterpret_cast<float4*>(C + (long)gm * ldc + gn0);
            cp[0] = make_float4(v[0], v[1], v[2], v[3]);
            cp[1] = make_float4(v[4], v[5], v[6], v[7]);
            if (C2) {
                float4* cp2 = reinterpret_cast<float4*>(C2 + (long)gm * ldc2 + gn0);
                cp2[0] = make_float4(v[0], v[1], v[2], v[3]);
                cp2[1] = make_float4(v[4], v[5], v[6], v[7]);
            }
            __syncwarp();
        }
    }
}

// ---------------- persistent RNN scan (fp32, batch-parallel) ----------------
__global__ void __launch_bounds__(256)
scan_kernel(const float* __restrict__ Xp, const float* __restrict__ WT,
            float* __restrict__ Hs)
{
    __shared__ __align__(16) float hs[4][NFEAT];
    const int tid = threadIdx.x;
    const int b0 = blockIdx.x * 4;
    const int n0 = tid * 2;

    for (int i = tid; i < 4 * NFEAT; i += 256) {
        int r = i >> 9, f = i & 511;
        float v = tanhf(Xp[((long)(b0 + r) * TTOT) * NFEAT + f]);
        hs[r][f] = v;
        Hs[((long)(b0 + r) * TSEQ) * NFEAT + f] = v;
    }
    __syncthreads();

    for (int t = 1; t < TSEQ; t++) {
        float acc[4][2];
        #pragma unroll
        for (int r = 0; r < 4; r++) { acc[r][0] = 0.f; acc[r][1] = 0.f; }

        #pragma unroll 4
        for (int k = 0; k < NFEAT; k += 4) {
            float4 h0 = *reinterpret_cast<const float4*>(&hs[0][k]);
            float4 h1 = *reinterpret_cast<const float4*>(&hs[1][k]);
            float4 h2 = *reinterpret_cast<const float4*>(&hs[2][k]);
            float4 h3 = *reinterpret_cast<const float4*>(&hs[3][k]);
            #pragma unroll
            for (int kk = 0; kk < 4; kk++) {
                float2 w = *reinterpret_cast<const float2*>(
                    &WT[(long)(k + kk) * NFEAT + n0]);
                float v0 = (kk == 0) ? h0.x : (kk == 1) ? h0.y : (kk == 2) ? h0.z : h0.w;
                float v1 = (kk == 0) ? h1.x : (kk == 1) ? h1.y : (kk == 2) ? h1.z : h1.w;
                float v2 = (kk == 0) ? h2.x : (kk == 1) ? h2.y : (kk == 2) ? h2.z : h2.w;
                float v3 = (kk == 0) ? h3.x : (kk == 1) ? h3.y : (kk == 2) ? h3.z : h3.w;
                acc[0][0] = fmaf(v0, w.x, acc[0][0]);
                acc[0][1] = fmaf(v0, w.y, acc[0][1]);
                acc[1][0] = fmaf(v1, w.x, acc[1][0]);
                acc[1][1] = fmaf(v1, w.y, acc[1][1]);
                acc[2][0] = fmaf(v2, w.x, acc[2][0]);
                acc[2][1] = fmaf(v2, w.y, acc[2][1]);
                acc[3][0] = fmaf(v3, w.x, acc[3][0]);
                acc[3][1] = fmaf(v3, w.y, acc[3][1]);
            }
        }
        __syncthreads();
        #pragma unroll
        for (int r = 0; r < 4; r++) {
            const float* xp = &Xp[((long)(b0 + r) * TTOT + t) * NFEAT + n0];
            float v0 = tanhf(xp[0] + acc[r][0]);
            float v1 = tanhf(xp[1] + acc[r][1]);
            hs[r][n0] = v0; hs[r][n0 + 1] = v1;
            float* hp = &Hs[((long)(b0 + r) * TSEQ + t) * NFEAT + n0];
            hp[0] = v0; hp[1] = v1;
        }
        __syncthreads();
    }
}

// ---------------- prep kernels (weights pre-rounded to tf32) ----------------
__global__ void init_kernel(const float* __restrict__ b_ih,
                            const float* __restrict__ b_hh,
                            float* __restrict__ bsum) {
    int i = threadIdx.x;
    if (i < NFEAT) bsum[i] = b_ih[i] + b_hh[i];
    if (i < 2) g_loss[i] = 0.0;
}

__global__ void transpose_kernel(const float* __restrict__ W,
                                 float* __restrict__ WT) {
    __shared__ float tile[32][33];
    int x = blockIdx.x * 32 + threadIdx.x;
    int y = blockIdx.y * 32 + threadIdx.y;
    #pragma unroll
    for (int j = 0; j < 32; j += 8)
        tile[threadIdx.y + j][threadIdx.x] = W[(long)(y + j) * NFEAT + x];
    __syncthreads();
    x = blockIdx.y * 32 + threadIdx.x;
    y = blockIdx.x * 32 + threadIdx.y;
    #pragma unroll
    for (int j = 0; j < 32; j += 8)
        WT[(long)(y + j) * NFEAT + x] = tile[threadIdx.x][threadIdx.y + j];
}

__global__ void wcat_kernel(const float* __restrict__ Wih,
                            const float* __restrict__ Whh,
                            float* __restrict__ Wcat) {
    int i = blockIdx.x * 256 + threadIdx.x;
    if (i < 512 * 1024) {
        int n = i >> 10, c = i & 1023;
        Wcat[i] = rnd_tf32((c < 512) ? Wih[n * 512 + c] : Whh[n * 512 + (c - 512)]);
    }
}

__global__ void round_copy(const float* __restrict__ src, float* __restrict__ dst,
                           int n) {
    int i = blockIdx.x * 256 + threadIdx.x;
    if (i < n) dst[i] = rnd_tf32(src[i]);
}

__global__ void pad_w1(const float* __restrict__ W1, float* __restrict__ W1p) {
    int i = blockIdx.x * 256 + threadIdx.x;
    if (i < HIDP * 512) { int n = i >> 9, k = i & 511;
        W1p[i] = (n < HID) ? rnd_tf32(W1[n * 512 + k]) : 0.f; }
}
__global__ void pad_w2(const float* __restrict__ W2, float* __restrict__ W2p) {
    int i = blockIdx.x * 256 + threadIdx.x;
    if (i < HIDP * HIDP) { int n = i >> 10, k = i & 1023;
        W2p[i] = (n < HID && k < HID) ? rnd_tf32(W2[n * HID + k]) : 0.f; }
}
__global__ void pad_w3(const float* __restrict__ W3, float* __restrict__ W3p) {
    int i = blockIdx.x * 256 + threadIdx.x;
    if (i < 512 * HIDP) { int n = i >> 10, k = i & 1023;
        W3p[i] = (k < HID) ? rnd_tf32(W3[n * HID + k]) : 0.f; }
}
__global__ void pad_params(const float* __restrict__ b, const float* __restrict__ g,
                           const float* __restrict__ be, const float* __restrict__ rm,
                           const float* __restrict__ rv, float* __restrict__ dst) {
    int i = blockIdx.x * 256 + threadIdx.x;
    if (i < HIDP) {
        bool v = i < HID;
        dst[i]            = v ? b[i]  : 0.f;
        dst[HIDP + i]     = v ? g[i]  : 0.f;
        dst[2 * HIDP + i] = v ? be[i] : 0.f;
        dst[3 * HIDP + i] = v ? rm[i] : 0.f;
        dst[4 * HIDP + i] = v ? rv[i] : 1.f;
    }
}

// ---------------- loss / gather kernels ----------------
__global__ void loss1_kernel(const float* __restrict__ Y, const float* __restrict__ x) {
    const long total = (long)BSZ * 63 * NFEAT;
    float local = 0.f;
    for (long e = (long)blockIdx.x * blockDim.x + threadIdx.x; e < total;
         e += (long)gridDim.x * blockDim.x) {
        int f  = (int)(e & 511);
        long bt = e >> 9;
        int tt = (int)(bt % 63);
        int b  = (int)(bt / 63);
        float yv = Y[((long)b * TSEQ + tt) * NFEAT + f];
        float xv = x[((long)b * TTOT + tt + 1) * NFEAT + f];
        float d = yv - xv;
        local += d * d;
    }
    float s = blockReduceSum(local);
    if (threadIdx.x == 0) atomicAdd(&g_loss[0], (double)s);
}

__global__ void seed_kernel(const float* __restrict__ Y,
                            const float* __restrict__ Hs,
                            float* __restrict__ S0) {
    int e = blockIdx.x * 256 + threadIdx.x;
    if (e < BSZ * NFEAT) {
        int b = e >> 9, f = e & 511;
        S0[(long)b * 1024 + f]       = Y [((long)b * TSEQ + (TSEQ - 1)) * NFEAT + f];
        S0[(long)b * 1024 + 512 + f] = Hs[((long)b * TSEQ + (TSEQ - 1)) * NFEAT + f];
    }
}

__global__ void final_kernel(const float* __restrict__ Xg, const float* __restrict__ x,
                             const int* __restrict__ t, float* __restrict__ out,
                             int out_size) {
    int e = blockIdx.x * blockDim.x + threadIdx.x;
    float local = 0.f;
    if (e < BSZ * NFEAT) {
        int b = e >> 9, f = e & 511;
        int gp = t[b] - 1;
        float v = Xg[(long)gp * BSZ * NFEAT + e];
        if (e < out_size) out[e] = v;
        float xf = x[((long)b * TTOT + TSEQ) * NFEAT + f];
        float d = v - xf;
        local = d * d;
    }
    float s = blockReduceSum(local);
    if (threadIdx.x == 0) atomicAdd(&g_loss[1], (double)s);
}

__global__ void write_loss_kernel(float* __restrict__ out, int out_size) {
    const double n1 = 16515072.0;
    const double n2 = 262144.0;
    double l = g_loss[0] / (n1 * n1) + g_loss[1] / (n2 * n2);
    for (int i = BSZ * NFEAT + threadIdx.x; i < out_size; i += blockDim.x)
        out[i] = (float)l;
}

// ---------------- host launchers ----------------
#define SMEM128 (2 * (128 + 128) * (32 + 8) * 4)   // 81920 B
#define SMEM64  (2 * (64 + 128) * (32 + 8) * 4)    // 61440 B

static inline void gemm128(const float* A, int lda, const float* W, int ldw,
                           float* C, int ldc, int M, int N, int K, int mode,
                           const float* bias, const float* g, const float* be,
                           const float* rm, const float* rv) {
    dim3 grid(N / 128, M / 128);
    tf32_gemm<128, 128, 32, 32, 64><<<grid, 256, SMEM128>>>(
        A, lda, W, ldw, C, ldc, nullptr, 0, M, N, K, mode, bias, g, be, rm, rv);
}

static inline void gemm64(const float* A, int lda, const float* W, int ldw,
                          float* C, int ldc, float* C2, int ldc2,
                          int M, int N, int K, int mode,
                          const float* bias, const float* g, const float* be,
                          const float* rm, const float* rv) {
    dim3 grid(N / 128, M / 64);
    tf32_gemm<64, 128, 32, 32, 32><<<grid, 256, SMEM64>>>(
        A, lda, W, ldw, C, ldc, C2, ldc2, M, N, K, mode, bias, g, be, rm, rv);
}

extern "C" void kernel_launch(void* const* d_in, const int* in_sizes, int n_in,
                              void* d_out, int out_size) {
    const float* x     = (const float*)d_in[0];
    const int*   t     = (const int*)  d_in[1];
    const float* W_ih  = (const float*)d_in[2];
    const float* W_hh  = (const float*)d_in[3];
    const float* b_ih  = (const float*)d_in[4];
    const float* b_hh  = (const float*)d_in[5];
    const float* W1    = (const float*)d_in[6];
    const float* b1    = (const float*)d_in[7];
    const float* g1    = (const float*)d_in[8];
    const float* beta1 = (const float*)d_in[9];
    const float* rm1   = (const float*)d_in[10];
    const float* rv1   = (const float*)d_in[11];
    const float* W2    = (const float*)d_in[12];
    const float* b2    = (const float*)d_in[13];
    const float* g2    = (const float*)d_in[14];
    const float* beta2 = (const float*)d_in[15];
    const float* rm2   = (const float*)d_in[16];
    const float* rv2   = (const float*)d_in[17];
    const float* W3    = (const float*)d_in[18];
    const float* b3    = (const float*)d_in[19];
    const float* g3    = (const float*)d_in[20];
    const float* beta3 = (const float*)d_in[21];
    const float* rm3   = (const float*)d_in[22];
    const float* rv3   = (const float*)d_in[23];
    float* out = (float*)d_out;

    // idempotent; executed every call (no static guards allowed)
    cudaFuncSetAttribute((const void*)tf32_gemm<128, 128, 32, 32, 64>,
                         cudaFuncAttributeMaxDynamicSharedMemorySize, SMEM128);
    cudaFuncSetAttribute((const void*)tf32_gemm<64, 128, 32, 32, 32>,
                         cudaFuncAttributeMaxDynamicSharedMemorySize, SMEM64);

    float* buf = nullptr;
    cudaGetSymbolAddress((void**)&buf, g_buf);

    float* Xp   = buf + OFF_XP;
    float* Hs   = buf + OFF_HS;
    float* Z1   = buf + OFF_Z1;
    float* Z2   = buf + OFF_Z2;
    float* Y    = buf + OFF_Y;
    float* W1p  = buf + OFF_W1P;
    float* W2p  = buf + OFF_W2P;
    float* W3p  = buf + OFF_W3P;
    float* Wcat = buf + OFF_WC;
    float* WT   = buf + OFF_WT;
    float* P1   = buf + OFF_P1;
    float* P2   = buf + OFF_P2;
    float* bsum = buf + OFF_BS;
    float* Wihr = buf + OFF_WIR;

    float *b1p = P1, *g1p = P1 + HIDP, *be1p = P1 + 2*HIDP, *rm1p = P1 + 3*HIDP, *rv1p = P1 + 4*HIDP;
    float *b2p = P2, *g2p = P2 + HIDP, *be2p = P2 + 2*HIDP, *rm2p = P2 + 3*HIDP, *rv2p = P2 + 4*HIDP;

    float* S0  = buf + DOFF_S0;
    float* S1  = buf + DOFF_S1;
    float* Z1d = buf + DOFF_Z1D;
    float* Z2d = buf + DOFF_Z2D;
    float* Xg  = buf + DOFF_XG;

    // 0. prep (weights tf32-rounded once)
    init_kernel<<<1, 512>>>(b_ih, b_hh, bsum);
    transpose_kernel<<<dim3(16, 16), dim3(32, 8)>>>(W_hh, WT);
    wcat_kernel<<<(512 * 1024 + 255) / 256, 256>>>(W_ih, W_hh, Wcat);
    round_copy<<<(512 * 512 + 255) / 256, 256>>>(W_ih, Wihr, 512 * 512);
    pad_w1<<<(HIDP * 512 + 255) / 256, 256>>>(W1, W1p);
    pad_w2<<<(HIDP * HIDP + 255) / 256, 256>>>(W2, W2p);
    pad_w3<<<(512 * HIDP + 255) / 256, 256>>>(W3, W3p);
    pad_params<<<(HIDP + 255) / 256, 256>>>(b1, g1, beta1, rm1, rv1, P1);
    pad_params<<<(HIDP + 255) / 256, 256>>>(b2, g2, beta2, rm2, rv2, P2);

    // 1. Xp = x @ W_ih^T + bsum
    gemm128(x, NFEAT, Wihr, NFEAT, Xp, NFEAT, BSZ * TTOT, NFEAT, NFEAT,
            0, bsum, nullptr, nullptr, nullptr, nullptr);

    // 2+3. persistent RNN scan
    scan_kernel<<<BSZ / 4, 256>>>(Xp, WT, Hs);

    // 4. autoencoder, chunked
    for (int c = 0; c < NCHUNK; c++) {
        const float* Ac = Hs + (long)c * MCH * NFEAT;
        float*       Yc = Y  + (long)c * MCH * NFEAT;
        gemm128(Ac, NFEAT, W1p, NFEAT, Z1, HIDP, MCH, HIDP, NFEAT,
                2, b1p, g1p, be1p, rm1p, rv1p);
        gemm128(Z1, HIDP, W2p, HIDP, Z2, HIDP, MCH, HIDP, HIDP,
                2, b2p, g2p, be2p, rm2p, rv2p);
        gemm128(Z2, HIDP, W3p, HIDP, Yc, NFEAT, MCH, NFEAT, HIDP,
                2, b3, g3, beta3, rm3, rv3);
    }

    // 5. loss1 + decode seed
    loss1_kernel<<<2048, 256>>>(Y, x);
    seed_kernel<<<(BSZ * NFEAT + 255) / 256, 256>>>(Y, Hs, S0);

    // 6. decode loop
    for (int g = 0; g < NGAP; g++) {
        float* Sin  = (g & 1) ? S1 : S0;
        float* Sout = (g & 1) ? S0 : S1;
        gemm64(Sin, 1024, Wcat, 1024, Sout + 512, 1024, nullptr, 0,
               BSZ, NFEAT, 1024, 3, bsum, nullptr, nullptr, nullptr, nullptr);
        gemm64(Sout + 512, 1024, W1p, NFEAT, Z1d, HIDP, nullptr, 0,
               BSZ, HIDP, NFEAT, 2, b1p, g1p, be1p, rm1p, rv1p);
        gemm64(Z1d, HIDP, W2p, HIDP, Z2d, HIDP, nullptr, 0,
               BSZ, HIDP, HIDP, 2, b2p, g2p, be2p, rm2p, rv2p);
        gemm64(Z2d, HIDP, W3p, HIDP, Xg + (long)g * BSZ * NFEAT, NFEAT, Sout, 1024,
               BSZ, NFEAT, HIDP, 2, b3, g3, beta3, rm3, rv3);
    }

    // 7+8. gather + losses
    final_kernel<<<(BSZ * NFEAT + 255) / 256, 256>>>(Xg, x, t, out, out_size);
    write_loss_kernel<<<1, 256>>>(out, out_size);
}